// round 4
// baseline (speedup 1.0000x reference)
#include <cuda_runtime.h>
#include <cuda_bf16.h>
#include <cuda_fp8.h>
#include <math.h>
#include <stdint.h>

// ---------------------------------------------------------------------------
// Mamba2 block: bf16 hi*hi + fp8 cross-term split-precision GEMMs + scan
//   D = Ah*Bh (bf16 HMMA) + [fp8(A)*fp8(Bl*256) + fp8(Al*256)*fp8(B)] * 2^-8
// ---------------------------------------------------------------------------

#define Bdim 4
#define Sdim 4096
#define Hdim 1024
#define Mrows (Bdim * Sdim)        // 16384
#define BSH   (Mrows * Hdim)
#define CHUNKS 64
#define CLEN   64

// -------------------- scratch (static __device__, no allocs) ---------------
__device__ __nv_bfloat16 g_xh[BSH];
__device__ uint8_t       g_x8[BSH];
__device__ uint8_t       g_xl8[BSH];
__device__ __nv_bfloat16 g_yh[BSH];
__device__ uint8_t       g_y8[BSH];
__device__ uint8_t       g_yl8[BSH];
__device__ __nv_bfloat16 g_w5h[5 * Hdim * Hdim];
__device__ uint8_t       g_w58[5 * Hdim * Hdim];
__device__ uint8_t       g_w5l8[5 * Hdim * Hdim];
__device__ __nv_bfloat16 g_woh[Hdim * Hdim];
__device__ uint8_t       g_wo8[Hdim * Hdim];
__device__ uint8_t       g_wol8[Hdim * Hdim];
__device__ float g_cont[BSH];
__device__ float g_ret[BSH];
__device__ float g_wg[BSH];
__device__ float g_rg[BSH];
__device__ float g_sk[BSH];
__device__ float g_Ac[Bdim * CHUNKS * Hdim];
__device__ float g_Bc[Bdim * CHUNKS * Hdim];
__device__ float g_Ss[Bdim * CHUNKS * Hdim];
__device__ float g_maskf[Mrows];
__device__ int   g_mask_mode;
__device__ float g_fs_dummy[Bdim * Hdim];

// -------------------- mask dtype detection + expansion ---------------------
__global__ void detect_mask_kernel(const unsigned char* __restrict__ mb, int n) {
    __shared__ int cflag[4];
    int t = threadIdx.x;
    if (t < 4) cflag[t] = 0;
    __syncthreads();
    for (int i = t; i < n; i += blockDim.x)
        if (mb[i]) atomicOr(&cflag[i & 3], 1);
    __syncthreads();
    if (t == 0) {
        int c0 = cflag[0], c1 = cflag[1], c2 = cflag[2], c3 = cflag[3];
        int mode = 0;
        if (c0 | c1 | c2 | c3) {
            if (c0 && !c1 && !c2 && !c3) mode = 1;
            else if (!c0 && !c1 && (c2 | c3)) mode = 2;
        }
        g_mask_mode = mode;
    }
}

__global__ void expand_mask_kernel(const void* __restrict__ mraw, int n) {
    int i = blockIdx.x * blockDim.x + threadIdx.x;
    if (i >= n) return;
    int mode = g_mask_mode;
    bool m;
    if (mode == 1)      m = ((const int*)mraw)[i] != 0;
    else if (mode == 2) m = ((const float*)mraw)[i] != 0.0f;
    else                m = ((const unsigned char*)mraw)[i] != 0;
    g_maskf[i] = m ? 1.0f : 0.0f;
}

// -------------------- fp32 -> bf16 hi + fp8(v) + fp8(lo*256) ---------------
__device__ __forceinline__ uint8_t to_e4m3(float v) {
    return (uint8_t)__nv_cvt_float_to_fp8(v, __NV_SATFINITE, __NV_E4M3);
}

__global__ void split_kernel(const float* __restrict__ in,
                             __nv_bfloat16* __restrict__ hi,
                             uint8_t* __restrict__ v8,
                             uint8_t* __restrict__ l8, int n) {
    int i = (blockIdx.x * blockDim.x + threadIdx.x) * 4;
    if (i >= n) return;
    float4 v = *(const float4*)(in + i);
    __nv_bfloat16 h0 = __float2bfloat16(v.x);
    __nv_bfloat16 h1 = __float2bfloat16(v.y);
    __nv_bfloat16 h2 = __float2bfloat16(v.z);
    __nv_bfloat16 h3 = __float2bfloat16(v.w);
    ((__nv_bfloat162*)(hi + i))[0] = __halves2bfloat162(h0, h1);
    ((__nv_bfloat162*)(hi + i))[1] = __halves2bfloat162(h2, h3);
    uchar4 q8 = make_uchar4(to_e4m3(v.x), to_e4m3(v.y),
                            to_e4m3(v.z), to_e4m3(v.w));
    *(uchar4*)(v8 + i) = q8;
    uchar4 ql = make_uchar4(
        to_e4m3((v.x - __bfloat162float(h0)) * 256.0f),
        to_e4m3((v.y - __bfloat162float(h1)) * 256.0f),
        to_e4m3((v.z - __bfloat162float(h2)) * 256.0f),
        to_e4m3((v.w - __bfloat162float(h3)) * 256.0f));
    *(uchar4*)(l8 + i) = ql;
}

// -------------------- PTX helpers ------------------------------------------
__device__ __forceinline__ uint32_t su32(const void* p) {
    uint32_t a;
    asm("{ .reg .u64 t; cvta.to.shared.u64 t, %1; cvt.u32.u64 %0, t; }"
        : "=r"(a) : "l"(p));
    return a;
}
__device__ __forceinline__ void cpa16(uint32_t s, const void* g) {
    asm volatile("cp.async.cg.shared.global [%0], [%1], 16;" :: "r"(s), "l"(g));
}
__device__ __forceinline__ void cpa_commit() {
    asm volatile("cp.async.commit_group;" ::: "memory");
}
__device__ __forceinline__ void cpa_wait1() {
    asm volatile("cp.async.wait_group 1;" ::: "memory");
}
__device__ __forceinline__ void cpa_wait0() {
    asm volatile("cp.async.wait_group 0;" ::: "memory");
}
__device__ __forceinline__ void ldm_x4(uint32_t* r, uint32_t addr) {
    asm volatile("ldmatrix.sync.aligned.m8n8.x4.shared.b16 {%0,%1,%2,%3}, [%4];"
                 : "=r"(r[0]), "=r"(r[1]), "=r"(r[2]), "=r"(r[3]) : "r"(addr));
}
__device__ __forceinline__ void mma_bf16(float* d, const uint32_t* a,
                                         const uint32_t* b) {
    asm volatile(
        "mma.sync.aligned.m16n8k16.row.col.f32.bf16.bf16.f32 "
        "{%0,%1,%2,%3}, {%4,%5,%6,%7}, {%8,%9}, {%0,%1,%2,%3};"
        : "+f"(d[0]), "+f"(d[1]), "+f"(d[2]), "+f"(d[3])
        : "r"(a[0]), "r"(a[1]), "r"(a[2]), "r"(a[3]), "r"(b[0]), "r"(b[1]));
}
__device__ __forceinline__ void mma_fp8(float* d, const uint32_t* a,
                                        const uint32_t* b) {
    asm volatile(
        "mma.sync.aligned.m16n8k32.row.col.f32.e4m3.e4m3.f32 "
        "{%0,%1,%2,%3}, {%4,%5,%6,%7}, {%8,%9}, {%0,%1,%2,%3};"
        : "+f"(d[0]), "+f"(d[1]), "+f"(d[2]), "+f"(d[3])
        : "r"(a[0]), "r"(a[1]), "r"(a[2]), "r"(a[3]), "r"(b[0]), "r"(b[1]));
}

// -------------------- GEMM: bf16 hi*hi + fp8 cross -------------------------
// BM=BN=128, BK=64, 256 threads, 8 warps (2x4), 2-stage cp.async pipeline.
// Stage smem: Ah(16K) Bh(16K) A8(8K) Al8(8K) B8(8K) Bl8(8K) = 64KB.

#define BF_TILE 16384
#define F8_TILE 8192
#define STAGE_BYTES 65536
#define SMEM_TOTAL (2 * STAGE_BYTES)   // 128 KB
#define NSTAGES (Hdim / 64)            // 16

struct GArgs {
    const __nv_bfloat16 *Ah, *Wh;
    const uint8_t *A8, *Al8, *W8, *Wl8;
    float*       outp[5];
    const float* bias[5];
    int          act[5];      // 0 none, 1 tanh, 2 sigmoid(+bias)
};

__device__ __forceinline__ uint32_t sw128(uint32_t base, int row, int chunk) {
    return base + row * 128 + ((chunk ^ (row & 7)) << 4);
}
__device__ __forceinline__ uint32_t sw64(uint32_t base, int row, int chunk) {
    return base + row * 64 + ((chunk ^ ((row >> 1) & 3)) << 4);
}

__global__ __launch_bounds__(256, 1)
void gemm_mma_kernel(GArgs ga) {
    extern __shared__ char smem[];
    uint32_t sb = su32(smem);
    int tid = threadIdx.x;
    int wid = tid >> 5, lane = tid & 31;
    int wm = wid >> 2, wn = wid & 3;           // 2 x 4 warp grid
    int m0 = wm * 64, n0 = wn * 32;            // warp tile 64x32

    int mBase = blockIdx.y * 128;
    int nBase = blockIdx.x * 128;
    const __nv_bfloat16* pAh = ga.Ah + (size_t)mBase * Hdim;
    const __nv_bfloat16* pBh = ga.Wh + (size_t)nBase * Hdim;
    const uint8_t* f8srcs[4] = {
        ga.A8  + (size_t)mBase * Hdim,
        ga.Al8 + (size_t)mBase * Hdim,
        ga.W8  + (size_t)nBase * Hdim,
        ga.Wl8 + (size_t)nBase * Hdim
    };

    float acc_h[4][4][4], acc_c[4][4][4];
#pragma unroll
    for (int i = 0; i < 4; i++)
#pragma unroll
        for (int j = 0; j < 4; j++)
#pragma unroll
            for (int e = 0; e < 4; e++) { acc_h[i][j][e] = 0.0f; acc_c[i][j][e] = 0.0f; }

    auto load_stage = [&](int s) {
        uint32_t so = sb + (s & 1) * STAGE_BYTES;
        int k0 = s * 64;
#pragma unroll
        for (int i = 0; i < 16; i++) {
            int c = tid + i * 256;             // 0..4095
            if (c < 2048) {                    // bf16: Ah then Bh (1024 chunks each)
                int T = c >> 10;
                int ct = c & 1023;
                int row = ct >> 3, col = ct & 7;
                const __nv_bfloat16* src = T ? pBh : pAh;
                cpa16(sw128(so + T * BF_TILE, row, col),
                      src + (size_t)row * Hdim + k0 + col * 8);
            } else {                           // fp8: A8, Al8, B8, Bl8 (512 each)
                int cc = c - 2048;
                int T = cc >> 9;
                int ct = cc & 511;
                int row = ct >> 2, col = ct & 3;
                cpa16(sw64(so + 2 * BF_TILE + T * F8_TILE, row, col),
                      f8srcs[T] + (size_t)row * Hdim + k0 + col * 16);
            }
        }
    };

    load_stage(0);
    cpa_commit();

    // bf16 ldmatrix lane addressing
    int aRow = (lane & 15);
    int aKC  = (lane >> 4);
    int bRow = (lane & 7) + ((lane >> 4) << 3);
    int bKC  = (lane >> 3) & 1;
    // fp8 ldmatrix lane addressing
    int fRow = (lane & 15);
    int fKC  = (lane >> 4);

    for (int s = 0; s < NSTAGES; s++) {
        if (s + 1 < NSTAGES) {
            load_stage(s + 1);
            cpa_commit();
            cpa_wait1();
        } else {
            cpa_wait0();
        }
        __syncthreads();

        uint32_t so  = sb + (s & 1) * STAGE_BYTES;
        uint32_t tAh = so;
        uint32_t tBh = so + BF_TILE;
        uint32_t tA8  = so + 2 * BF_TILE;
        uint32_t tAl8 = tA8 + F8_TILE;
        uint32_t tB8  = tA8 + 2 * F8_TILE;
        uint32_t tBl8 = tA8 + 3 * F8_TILE;

        // ---- bf16 hi*hi: 4 k16 steps ----
#pragma unroll
        for (int kk = 0; kk < 4; kk++) {
            int kc = kk * 2;
            uint32_t bh[8];
#pragma unroll
            for (int half = 0; half < 2; half++)
                ldm_x4(bh + half * 4, sw128(tBh, n0 + half * 16 + bRow, kc + bKC));
#pragma unroll
            for (int mf = 0; mf < 4; mf++) {
                uint32_t ah[4];
                ldm_x4(ah, sw128(tAh, m0 + mf * 16 + aRow, kc + aKC));
#pragma unroll
                for (int nf = 0; nf < 4; nf++)
                    mma_bf16(acc_h[mf][nf], ah, bh + (nf >> 1) * 4 + (nf & 1) * 2);
            }
        }

        // ---- fp8 cross: 2 k32 steps ----
#pragma unroll
        for (int ks = 0; ks < 2; ks++) {
            int fc = ks * 2 + fKC;
            uint32_t b8f[8], b8l[8];
#pragma unroll
            for (int half = 0; half < 2; half++) {
                ldm_x4(b8f + half * 4, sw64(tB8,  n0 + half * 16 + fRow, fc));
                ldm_x4(b8l + half * 4, sw64(tBl8, n0 + half * 16 + fRow, fc));
            }
#pragma unroll
            for (int mf = 0; mf < 4; mf++) {
                uint32_t a8[4], al8[4];
                ldm_x4(a8,  sw64(tA8,  m0 + mf * 16 + fRow, fc));
                ldm_x4(al8, sw64(tAl8, m0 + mf * 16 + fRow, fc));
#pragma unroll
                for (int nf = 0; nf < 4; nf++) {
                    int h = nf >> 1, sub = nf & 1;
                    uint32_t bf2[2] = {b8f[h * 4 + sub], b8f[h * 4 + sub + 2]};
                    uint32_t bl2[2] = {b8l[h * 4 + sub], b8l[h * 4 + sub + 2]};
                    mma_fp8(acc_c[mf][nf], a8,  bl2);
                    mma_fp8(acc_c[mf][nf], al8, bf2);
                }
            }
        }
        __syncthreads();
    }

    // ---------------- epilogue: merge + activation + fp32 store -------------
    int p = nBase >> 10;
    float* __restrict__ outp = ga.outp[p];
    const float* __restrict__ bias = ga.bias[p];
    int act = ga.act[p];
    int ocol0 = (nBase & 1023) + n0;
    const float inv256 = 1.0f / 256.0f;

#pragma unroll
    for (int mf = 0; mf < 4; mf++) {
#pragma unroll
        for (int rh = 0; rh < 2; rh++) {
            int m = mBase + m0 + mf * 16 + (lane >> 2) + rh * 8;
#pragma unroll
            for (int nf = 0; nf < 4; nf++) {
                int col = ocol0 + nf * 8 + (lane & 3) * 2;
                float v0 = acc_h[mf][nf][rh * 2 + 0] + acc_c[mf][nf][rh * 2 + 0] * inv256;
                float v1 = acc_h[mf][nf][rh * 2 + 1] + acc_c[mf][nf][rh * 2 + 1] * inv256;
                if (act == 1) {
                    v0 = tanhf(v0);
                    v1 = tanhf(v1);
                } else if (act == 2) {
                    v0 = 1.0f / (1.0f + expf(-(v0 + bias[col])));
                    v1 = 1.0f / (1.0f + expf(-(v1 + bias[col + 1])));
                }
                *(float2*)(outp + (size_t)m * Hdim + col) = make_float2(v0, v1);
            }
        }
    }
}

// -------------------- chunked parallel linear scan -------------------------
__global__ void scan_stage1() {
    int id = blockIdx.x * blockDim.x + threadIdx.x;
    int h = id & (Hdim - 1);
    int j = (id >> 10) & (CHUNKS - 1);
    int b = id >> 16;
    float A = 1.0f, Bc = 0.0f;
    size_t base = (size_t)b * Sdim * Hdim + h;
    int s0 = j * CLEN;
#pragma unroll 4
    for (int t = 0; t < CLEN; t++) {
        int s = s0 + t;
        size_t idx = base + (size_t)s * Hdim;
        float a  = g_ret[idx];
        float m  = g_maskf[b * Sdim + s];
        float bx = (1.0f - a) * g_wg[idx] * g_cont[idx];
        float aa = 1.0f + m * (a - 1.0f);
        float bb = m * bx;
        A *= aa;
        Bc = fmaf(aa, Bc, bb);
    }
    int cidx = (b * CHUNKS + j) * Hdim + h;
    g_Ac[cidx] = A;
    g_Bc[cidx] = Bc;
}

__global__ void scan_stage2(const float* __restrict__ state,
                            float* __restrict__ fs_out) {
    int id = blockIdx.x * blockDim.x + threadIdx.x;
    int h = id & (Hdim - 1);
    int b = id >> 10;
    float st = state[id];
#pragma unroll
    for (int j = 0; j < CHUNKS; j++) {
        int cidx = (b * CHUNKS + j) * Hdim + h;
        g_Ss[cidx] = st;
        st = fmaf(g_Ac[cidx], st, g_Bc[cidx]);
    }
    fs_out[id] = st;
}

__global__ void scan_stage3() {
    int id = blockIdx.x * blockDim.x + threadIdx.x;
    int h = id & (Hdim - 1);
    int j = (id >> 10) & (CHUNKS - 1);
    int b = id >> 16;
    float st = g_Ss[(b * CHUNKS + j) * Hdim + h];
    size_t base = (size_t)b * Sdim * Hdim + h;
    int s0 = j * CLEN;
#pragma unroll 4
    for (int t = 0; t < CLEN; t++) {
        int s = s0 + t;
        size_t idx = base + (size_t)s * Hdim;
        float a  = g_ret[idx];
        float m  = g_maskf[b * Sdim + s];
        float bx = (1.0f - a) * g_wg[idx] * g_cont[idx];
        float aa = 1.0f + m * (a - 1.0f);
        float bb = m * bx;
        st = fmaf(aa, st, bb);
        float yv = m * fmaf(g_rg[idx], st, g_sk[idx]);
        __nv_bfloat16 hh = __float2bfloat16(yv);
        g_yh[idx] = hh;
        g_y8[idx] = to_e4m3(yv);
        g_yl8[idx] = to_e4m3((yv - __bfloat162float(hh)) * 256.0f);
    }
}

// -------------------- launch -----------------------------------------------
extern "C" void kernel_launch(void* const* d_in, const int* in_sizes, int n_in,
                              void* d_out, int out_size) {
    const float* x     = (const float*)d_in[0];
    const float* state = (const float*)d_in[1];
    const void*  mask  = d_in[2];
    const float* W_in  = (const float*)d_in[3];
    const float* W_a   = (const float*)d_in[4];
    const float* b_a   = (const float*)d_in[5];
    const float* W_b   = (const float*)d_in[6];
    const float* b_b   = (const float*)d_in[7];
    const float* W_c   = (const float*)d_in[8];
    const float* b_c   = (const float*)d_in[9];
    const float* W_d   = (const float*)d_in[10];
    const float* W_out = (const float*)d_in[11];
    float* out = (float*)d_out;

    __nv_bfloat16 *p_xh, *p_yh, *p_w5h, *p_woh;
    uint8_t *p_x8, *p_xl8, *p_y8, *p_yl8, *p_w58, *p_w5l8, *p_wo8, *p_wol8;
    float *p_cont, *p_ret, *p_wg, *p_rg, *p_sk, *p_fsdummy;
    cudaGetSymbolAddress((void**)&p_xh,   g_xh);
    cudaGetSymbolAddress((void**)&p_x8,   g_x8);
    cudaGetSymbolAddress((void**)&p_xl8,  g_xl8);
    cudaGetSymbolAddress((void**)&p_yh,   g_yh);
    cudaGetSymbolAddress((void**)&p_y8,   g_y8);
    cudaGetSymbolAddress((void**)&p_yl8,  g_yl8);
    cudaGetSymbolAddress((void**)&p_w5h,  g_w5h);
    cudaGetSymbolAddress((void**)&p_w58,  g_w58);
    cudaGetSymbolAddress((void**)&p_w5l8, g_w5l8);
    cudaGetSymbolAddress((void**)&p_woh,  g_woh);
    cudaGetSymbolAddress((void**)&p_wo8,  g_wo8);
    cudaGetSymbolAddress((void**)&p_wol8, g_wol8);
    cudaGetSymbolAddress((void**)&p_cont, g_cont);
    cudaGetSymbolAddress((void**)&p_ret,  g_ret);
    cudaGetSymbolAddress((void**)&p_wg,   g_wg);
    cudaGetSymbolAddress((void**)&p_rg,   g_rg);
    cudaGetSymbolAddress((void**)&p_sk,   g_sk);
    cudaGetSymbolAddress((void**)&p_fsdummy, g_fs_dummy);

    cudaFuncSetAttribute(gemm_mma_kernel,
                         cudaFuncAttributeMaxDynamicSharedMemorySize, SMEM_TOTAL);

    // mask canonicalization
    detect_mask_kernel<<<1, 256>>>((const unsigned char*)mask, Mrows);
    expand_mask_kernel<<<Mrows / 256, 256>>>(mask, Mrows);

    // splits
    const size_t WN = (size_t)Hdim * Hdim;
    split_kernel<<<BSH / 4 / 256, 256>>>(x, p_xh, p_x8, p_xl8, BSH);
    split_kernel<<<WN / 4 / 256, 256>>>(W_in, p_w5h + 0 * WN, p_w58 + 0 * WN, p_w5l8 + 0 * WN, WN);
    split_kernel<<<WN / 4 / 256, 256>>>(W_a,  p_w5h + 1 * WN, p_w58 + 1 * WN, p_w5l8 + 1 * WN, WN);
    split_kernel<<<WN / 4 / 256, 256>>>(W_b,  p_w5h + 2 * WN, p_w58 + 2 * WN, p_w5l8 + 2 * WN, WN);
    split_kernel<<<WN / 4 / 256, 256>>>(W_c,  p_w5h + 3 * WN, p_w58 + 3 * WN, p_w5l8 + 3 * WN, WN);
    split_kernel<<<WN / 4 / 256, 256>>>(W_d,  p_w5h + 4 * WN, p_w58 + 4 * WN, p_w5l8 + 4 * WN, WN);
    split_kernel<<<WN / 4 / 256, 256>>>(W_out, p_woh, p_wo8, p_wol8, WN);

    // Phase 1: fused 5-projection GEMM
    GArgs g1;
    g1.Ah = p_xh; g1.A8 = p_x8; g1.Al8 = p_xl8;
    g1.Wh = p_w5h; g1.W8 = p_w58; g1.Wl8 = p_w5l8;
    g1.outp[0] = p_cont; g1.outp[1] = p_ret; g1.outp[2] = p_wg;
    g1.outp[3] = p_rg;   g1.outp[4] = p_sk;
    g1.bias[0] = nullptr; g1.bias[1] = b_a; g1.bias[2] = b_b;
    g1.bias[3] = b_c;     g1.bias[4] = nullptr;
    g1.act[0] = 1; g1.act[1] = 2; g1.act[2] = 2; g1.act[3] = 2; g1.act[4] = 0;
    gemm_mma_kernel<<<dim3(40, 128), 256, SMEM_TOTAL>>>(g1);

    // Phase 2: chunked scan
    float* fsPtr = (out_size >= BSH + Bdim * Hdim) ? (out + BSH) : p_fsdummy;
    scan_stage1<<<(Bdim * CHUNKS * Hdim) / 256, 256>>>();
    scan_stage2<<<(Bdim * Hdim) / 256, 256>>>(state, fsPtr);
    scan_stage3<<<(Bdim * CHUNKS * Hdim) / 256, 256>>>();

    // Phase 3: output GEMM
    GArgs g2;
    g2.Ah = p_yh; g2.A8 = p_y8; g2.Al8 = p_yl8;
    g2.Wh = p_woh; g2.W8 = p_wo8; g2.Wl8 = p_wol8;
    for (int i = 0; i < 5; i++) {
        g2.outp[i] = out; g2.bias[i] = nullptr; g2.act[i] = 0;
    }
    gemm_mma_kernel<<<dim3(8, 128), 256, SMEM_TOTAL>>>(g2);
}

// round 7
// speedup vs baseline: 1.6127x; 1.6127x over previous
#include <cuda_runtime.h>
#include <cuda_bf16.h>
#include <cuda_fp16.h>
#include <math.h>
#include <stdint.h>

// ---------------------------------------------------------------------------
// Mamba2 block: fp16 dual-split-weight GEMMs (2 HMMA products, 1 accumulator)
//   D = x1*W1 + x1*W2,  W1=fp16(W), W2=fp16(W-W1)  ->  err ~ fp16 quant of x
// ---------------------------------------------------------------------------

#define Bdim 4
#define Sdim 4096
#define Hdim 1024
#define Mrows (Bdim * Sdim)        // 16384
#define BSH   (Mrows * Hdim)
#define CHUNKS 64
#define CLEN   64

// -------------------- scratch (static __device__, no allocs) ---------------
__device__ __half g_x1[BSH];
__device__ __half g_y1[BSH];
__device__ __half g_w51[5 * Hdim * Hdim];
__device__ __half g_w52[5 * Hdim * Hdim];
__device__ __half g_wo1[Hdim * Hdim];
__device__ __half g_wo2[Hdim * Hdim];
__device__ float g_cont[BSH];
__device__ float g_ret[BSH];
__device__ float g_wg[BSH];
__device__ float g_rg[BSH];
__device__ float g_sk[BSH];
__device__ float g_Ac[Bdim * CHUNKS * Hdim];
__device__ float g_Bc[Bdim * CHUNKS * Hdim];
__device__ float g_Ss[Bdim * CHUNKS * Hdim];
__device__ float g_maskf[Mrows];
__device__ int   g_mask_mode;
__device__ float g_fs_dummy[Bdim * Hdim];

// -------------------- mask dtype detection + expansion ---------------------
__global__ void detect_mask_kernel(const unsigned char* __restrict__ mb, int n) {
    __shared__ int cflag[4];
    int t = threadIdx.x;
    if (t < 4) cflag[t] = 0;
    __syncthreads();
    for (int i = t; i < n; i += blockDim.x)
        if (mb[i]) atomicOr(&cflag[i & 3], 1);
    __syncthreads();
    if (t == 0) {
        int c0 = cflag[0], c1 = cflag[1], c2 = cflag[2], c3 = cflag[3];
        int mode = 0;
        if (c0 | c1 | c2 | c3) {
            if (c0 && !c1 && !c2 && !c3) mode = 1;
            else if (!c0 && !c1 && (c2 | c3)) mode = 2;
        }
        g_mask_mode = mode;
    }
}

__global__ void expand_mask_kernel(const void* __restrict__ mraw, int n) {
    int i = blockIdx.x * blockDim.x + threadIdx.x;
    if (i >= n) return;
    int mode = g_mask_mode;
    bool m;
    if (mode == 1)      m = ((const int*)mraw)[i] != 0;
    else if (mode == 2) m = ((const float*)mraw)[i] != 0.0f;
    else                m = ((const unsigned char*)mraw)[i] != 0;
    g_maskf[i] = m ? 1.0f : 0.0f;
}

// -------------------- conversion kernels ------------------------------------
__global__ void split_w_kernel(const float* __restrict__ in,
                               __half* __restrict__ w1,
                               __half* __restrict__ w2, int n) {
    int i = (blockIdx.x * blockDim.x + threadIdx.x) * 4;
    if (i >= n) return;
    float4 v = *(const float4*)(in + i);
    __half a0 = __float2half_rn(v.x);
    __half a1 = __float2half_rn(v.y);
    __half a2 = __float2half_rn(v.z);
    __half a3 = __float2half_rn(v.w);
    ((__half2*)(w1 + i))[0] = __halves2half2(a0, a1);
    ((__half2*)(w1 + i))[1] = __halves2half2(a2, a3);
    ((__half2*)(w2 + i))[0] = __halves2half2(
        __float2half_rn(v.x - __half2float(a0)),
        __float2half_rn(v.y - __half2float(a1)));
    ((__half2*)(w2 + i))[1] = __halves2half2(
        __float2half_rn(v.z - __half2float(a2)),
        __float2half_rn(v.w - __half2float(a3)));
}

__global__ void cvt_x_kernel(const float* __restrict__ in,
                             __half* __restrict__ x1, int n) {
    int i = (blockIdx.x * blockDim.x + threadIdx.x) * 4;
    if (i >= n) return;
    float4 v = *(const float4*)(in + i);
    ((__half2*)(x1 + i))[0] = __halves2half2(__float2half_rn(v.x), __float2half_rn(v.y));
    ((__half2*)(x1 + i))[1] = __halves2half2(__float2half_rn(v.z), __float2half_rn(v.w));
}

// -------------------- PTX helpers ------------------------------------------
__device__ __forceinline__ uint32_t su32(const void* p) {
    uint32_t a;
    asm("{ .reg .u64 t; cvta.to.shared.u64 t, %1; cvt.u32.u64 %0, t; }"
        : "=r"(a) : "l"(p));
    return a;
}
__device__ __forceinline__ void cpa16(uint32_t s, const void* g) {
    asm volatile("cp.async.cg.shared.global [%0], [%1], 16;" :: "r"(s), "l"(g));
}
__device__ __forceinline__ void cpa_commit() {
    asm volatile("cp.async.commit_group;" ::: "memory");
}
__device__ __forceinline__ void cpa_wait1() {
    asm volatile("cp.async.wait_group 1;" ::: "memory");
}
__device__ __forceinline__ void cpa_wait0() {
    asm volatile("cp.async.wait_group 0;" ::: "memory");
}
__device__ __forceinline__ void ldm_x4(uint32_t* r, uint32_t addr) {
    asm volatile("ldmatrix.sync.aligned.m8n8.x4.shared.b16 {%0,%1,%2,%3}, [%4];"
                 : "=r"(r[0]), "=r"(r[1]), "=r"(r[2]), "=r"(r[3]) : "r"(addr));
}
__device__ __forceinline__ void mma_f16(float* d, const uint32_t* a,
                                        const uint32_t* b) {
    asm volatile(
        "mma.sync.aligned.m16n8k16.row.col.f32.f16.f16.f32 "
        "{%0,%1,%2,%3}, {%4,%5,%6,%7}, {%8,%9}, {%0,%1,%2,%3};"
        : "+f"(d[0]), "+f"(d[1]), "+f"(d[2]), "+f"(d[3])
        : "r"(a[0]), "r"(a[1]), "r"(a[2]), "r"(a[3]), "r"(b[0]), "r"(b[1]));
}

// -------------------- GEMM: fp16 dual-split weights --------------------------
// BM=BN=128, BK=64, 256 threads, 8 warps (2x4 of 64x32), 3-stage pipeline.
// Stage smem: A(16K) W1(16K) W2(16K) = 48KB; 3 stages = 144KB.

#define TILE_BYTES 16384
#define STAGE_BYTES 49152
#define SMEM_TOTAL (3 * STAGE_BYTES)   // 147456
#define NSTAGES (Hdim / 64)            // 16

struct GArgs {
    const __half *A1, *W1, *W2;
    float*       outp[5];
    const float* bias[5];
    int          act[5];      // 0 none, 1 tanh, 2 sigmoid(+bias)
};

__device__ __forceinline__ uint32_t sw128(uint32_t base, int row, int chunk) {
    return base + row * 128 + ((chunk ^ (row & 7)) << 4);
}

__global__ __launch_bounds__(256, 1)
void gemm_mma_kernel(GArgs ga) {
    extern __shared__ char smem[];
    uint32_t sb = su32(smem);
    int tid = threadIdx.x;
    int wid = tid >> 5, lane = tid & 31;
    int wm = wid >> 2, wn = wid & 3;           // 2 x 4 warp grid
    int m0 = wm * 64, n0 = wn * 32;            // warp tile 64x32

    int mBase = blockIdx.y * 128;
    int nBase = blockIdx.x * 128;
    const __half* pA  = ga.A1 + (size_t)mBase * Hdim;
    const __half* pW1 = ga.W1 + (size_t)nBase * Hdim;
    const __half* pW2 = ga.W2 + (size_t)nBase * Hdim;

    float acc[4][4][4];
#pragma unroll
    for (int i = 0; i < 4; i++)
#pragma unroll
        for (int j = 0; j < 4; j++)
#pragma unroll
            for (int e = 0; e < 4; e++) acc[i][j][e] = 0.0f;

    auto load_stage = [&](int s) {
        uint32_t so = sb + (s % 3) * STAGE_BYTES;
        int k0 = s * 64;
#pragma unroll
        for (int i = 0; i < 12; i++) {
            int c = tid + i * 256;             // 0..3071
            int T = c >> 10;                   // 0=A 1=W1 2=W2
            int ct = c & 1023;
            int row = ct >> 3, col = ct & 7;
            const __half* src = (T == 0) ? pA : (T == 1) ? pW1 : pW2;
            cpa16(sw128(so + T * TILE_BYTES, row, col),
                  src + (size_t)row * Hdim + k0 + col * 8);
        }
        cpa_commit();
    };

    load_stage(0);
    load_stage(1);

    // ldmatrix lane addressing (128B rows)
    int aRow = (lane & 15);
    int aKC  = (lane >> 4);
    int bRow = (lane & 7) + ((lane >> 4) << 3);
    int bKC  = (lane >> 3) & 1;

    for (int s = 0; s < NSTAGES; s++) {
        if (s + 2 < NSTAGES) cpa_wait1();
        else if (s + 1 < NSTAGES) cpa_wait1();
        else cpa_wait0();
        __syncthreads();

        uint32_t so  = sb + (s % 3) * STAGE_BYTES;
        uint32_t tA  = so;
        uint32_t tW1 = so + TILE_BYTES;
        uint32_t tW2 = so + 2 * TILE_BYTES;

#pragma unroll
        for (int kk = 0; kk < 4; kk++) {
            int kc = kk * 2;
            uint32_t b1[8], b2[8];
#pragma unroll
            for (int half = 0; half < 2; half++) {
                ldm_x4(b1 + half * 4, sw128(tW1, n0 + half * 16 + bRow, kc + bKC));
                ldm_x4(b2 + half * 4, sw128(tW2, n0 + half * 16 + bRow, kc + bKC));
            }
#pragma unroll
            for (int mf = 0; mf < 4; mf++) {
                uint32_t a[4];
                ldm_x4(a, sw128(tA, m0 + mf * 16 + aRow, kc + aKC));
#pragma unroll
                for (int nf = 0; nf < 4; nf++) {
                    mma_f16(acc[mf][nf], a, b1 + (nf >> 1) * 4 + (nf & 1) * 2);
                    mma_f16(acc[mf][nf], a, b2 + (nf >> 1) * 4 + (nf & 1) * 2);
                }
            }
        }
        __syncthreads();
        if (s + 2 < NSTAGES) load_stage(s + 2);
    }

    // ---------------- epilogue: activation + fp32 store ----------------
    int p = nBase >> 10;
    float* __restrict__ outp = ga.outp[p];
    const float* __restrict__ bias = ga.bias[p];
    int act = ga.act[p];
    int ocol0 = (nBase & 1023) + n0;

#pragma unroll
    for (int mf = 0; mf < 4; mf++) {
#pragma unroll
        for (int rh = 0; rh < 2; rh++) {
            int m = mBase + m0 + mf * 16 + (lane >> 2) + rh * 8;
#pragma unroll
            for (int nf = 0; nf < 4; nf++) {
                int col = ocol0 + nf * 8 + (lane & 3) * 2;
                float v0 = acc[mf][nf][rh * 2 + 0];
                float v1 = acc[mf][nf][rh * 2 + 1];
                if (act == 1) {
                    v0 = tanhf(v0);
                    v1 = tanhf(v1);
                } else if (act == 2) {
                    v0 = 1.0f / (1.0f + expf(-(v0 + bias[col])));
                    v1 = 1.0f / (1.0f + expf(-(v1 + bias[col + 1])));
                }
                *(float2*)(outp + (size_t)m * Hdim + col) = make_float2(v0, v1);
            }
        }
    }
}

// -------------------- chunked parallel linear scan -------------------------
__global__ void scan_stage1() {
    int id = blockIdx.x * blockDim.x + threadIdx.x;
    int h = id & (Hdim - 1);
    int j = (id >> 10) & (CHUNKS - 1);
    int b = id >> 16;
    float A = 1.0f, Bc = 0.0f;
    size_t base = (size_t)b * Sdim * Hdim + h;
    int s0 = j * CLEN;
#pragma unroll 4
    for (int t = 0; t < CLEN; t++) {
        int s = s0 + t;
        size_t idx = base + (size_t)s * Hdim;
        float a  = g_ret[idx];
        float m  = g_maskf[b * Sdim + s];
        float bx = (1.0f - a) * g_wg[idx] * g_cont[idx];
        float aa = 1.0f + m * (a - 1.0f);
        float bb = m * bx;
        A *= aa;
        Bc = fmaf(aa, Bc, bb);
    }
    int cidx = (b * CHUNKS + j) * Hdim + h;
    g_Ac[cidx] = A;
    g_Bc[cidx] = Bc;
}

__global__ void scan_stage2(const float* __restrict__ state,
                            float* __restrict__ fs_out) {
    int id = blockIdx.x * blockDim.x + threadIdx.x;
    int h = id & (Hdim - 1);
    int b = id >> 10;
    float st = state[id];
#pragma unroll
    for (int j = 0; j < CHUNKS; j++) {
        int cidx = (b * CHUNKS + j) * Hdim + h;
        g_Ss[cidx] = st;
        st = fmaf(g_Ac[cidx], st, g_Bc[cidx]);
    }
    fs_out[id] = st;
}

__global__ void scan_stage3() {
    int id = blockIdx.x * blockDim.x + threadIdx.x;
    int h = id & (Hdim - 1);
    int j = (id >> 10) & (CHUNKS - 1);
    int b = id >> 16;
    float st = g_Ss[(b * CHUNKS + j) * Hdim + h];
    size_t base = (size_t)b * Sdim * Hdim + h;
    int s0 = j * CLEN;
#pragma unroll 4
    for (int t = 0; t < CLEN; t++) {
        int s = s0 + t;
        size_t idx = base + (size_t)s * Hdim;
        float a  = g_ret[idx];
        float m  = g_maskf[b * Sdim + s];
        float bx = (1.0f - a) * g_wg[idx] * g_cont[idx];
        float aa = 1.0f + m * (a - 1.0f);
        float bb = m * bx;
        st = fmaf(aa, st, bb);
        float yv = m * fmaf(g_rg[idx], st, g_sk[idx]);
        g_y1[idx] = __float2half_rn(yv);
    }
}

// -------------------- launch -----------------------------------------------
extern "C" void kernel_launch(void* const* d_in, const int* in_sizes, int n_in,
                              void* d_out, int out_size) {
    const float* x     = (const float*)d_in[0];
    const float* state = (const float*)d_in[1];
    const void*  mask  = d_in[2];
    const float* W_in  = (const float*)d_in[3];
    const float* W_a   = (const float*)d_in[4];
    const float* b_a   = (const float*)d_in[5];
    const float* W_b   = (const float*)d_in[6];
    const float* b_b   = (const float*)d_in[7];
    const float* W_c   = (const float*)d_in[8];
    const float* b_c   = (const float*)d_in[9];
    const float* W_d   = (const float*)d_in[10];
    const float* W_out = (const float*)d_in[11];
    float* out = (float*)d_out;

    __half *p_x1, *p_y1, *p_w51, *p_w52, *p_wo1, *p_wo2;
    float *p_cont, *p_ret, *p_wg, *p_rg, *p_sk, *p_fsdummy;
    cudaGetSymbolAddress((void**)&p_x1,  g_x1);
    cudaGetSymbolAddress((void**)&p_y1,  g_y1);
    cudaGetSymbolAddress((void**)&p_w51, g_w51);
    cudaGetSymbolAddress((void**)&p_w52, g_w52);
    cudaGetSymbolAddress((void**)&p_wo1, g_wo1);
    cudaGetSymbolAddress((void**)&p_wo2, g_wo2);
    cudaGetSymbolAddress((void**)&p_cont, g_cont);
    cudaGetSymbolAddress((void**)&p_ret,  g_ret);
    cudaGetSymbolAddress((void**)&p_wg,   g_wg);
    cudaGetSymbolAddress((void**)&p_rg,   g_rg);
    cudaGetSymbolAddress((void**)&p_sk,   g_sk);
    cudaGetSymbolAddress((void**)&p_fsdummy, g_fs_dummy);

    cudaFuncSetAttribute(gemm_mma_kernel,
                         cudaFuncAttributeMaxDynamicSharedMemorySize, SMEM_TOTAL);

    // mask canonicalization
    detect_mask_kernel<<<1, 256>>>((const unsigned char*)mask, Mrows);
    expand_mask_kernel<<<Mrows / 256, 256>>>(mask, Mrows);

    // conversions
    const size_t WN = (size_t)Hdim * Hdim;
    cvt_x_kernel<<<BSH / 4 / 256, 256>>>(x, p_x1, BSH);
    split_w_kernel<<<WN / 4 / 256, 256>>>(W_in, p_w51 + 0 * WN, p_w52 + 0 * WN, WN);
    split_w_kernel<<<WN / 4 / 256, 256>>>(W_a,  p_w51 + 1 * WN, p_w52 + 1 * WN, WN);
    split_w_kernel<<<WN / 4 / 256, 256>>>(W_b,  p_w51 + 2 * WN, p_w52 + 2 * WN, WN);
    split_w_kernel<<<WN / 4 / 256, 256>>>(W_c,  p_w51 + 3 * WN, p_w52 + 3 * WN, WN);
    split_w_kernel<<<WN / 4 / 256, 256>>>(W_d,  p_w51 + 4 * WN, p_w52 + 4 * WN, WN);
    split_w_kernel<<<WN / 4 / 256, 256>>>(W_out, p_wo1, p_wo2, WN);

    // Phase 1: fused 5-projection GEMM
    GArgs g1;
    g1.A1 = p_x1; g1.W1 = p_w51; g1.W2 = p_w52;
    g1.outp[0] = p_cont; g1.outp[1] = p_ret; g1.outp[2] = p_wg;
    g1.outp[3] = p_rg;   g1.outp[4] = p_sk;
    g1.bias[0] = nullptr; g1.bias[1] = b_a; g1.bias[2] = b_b;
    g1.bias[3] = b_c;     g1.bias[4] = nullptr;
    g1.act[0] = 1; g1.act[1] = 2; g1.act[2] = 2; g1.act[3] = 2; g1.act[4] = 0;
    gemm_mma_kernel<<<dim3(40, 128), 256, SMEM_TOTAL>>>(g1);

    // Phase 2: chunked scan
    float* fsPtr = (out_size >= BSH + Bdim * Hdim) ? (out + BSH) : p_fsdummy;
    scan_stage1<<<(Bdim * CHUNKS * Hdim) / 256, 256>>>();
    scan_stage2<<<(Bdim * Hdim) / 256, 256>>>(state, fsPtr);
    scan_stage3<<<(Bdim * CHUNKS * Hdim) / 256, 256>>>();

    // Phase 3: output GEMM
    GArgs g2;
    g2.A1 = p_y1; g2.W1 = p_wo1; g2.W2 = p_wo2;
    for (int i = 0; i < 5; i++) {
        g2.outp[i] = out; g2.bias[i] = nullptr; g2.act[i] = 0;
    }
    gemm_mma_kernel<<<dim3(8, 128), 256, SMEM_TOTAL>>>(g2);
}

// round 8
// speedup vs baseline: 2.9413x; 1.8238x over previous
#include <cuda_runtime.h>
#include <cuda_bf16.h>
#include <cuda_fp16.h>
#include <math.h>
#include <stdint.h>

// ---------------------------------------------------------------------------
// Mamba2 block: single-product fp16 HMMA GEMMs + chunked scan
//   D = fp16(x) * fp16(W),  fp32 accumulate  (err ~ sqrt2 * fp16 quant)
// ---------------------------------------------------------------------------

#define Bdim 4
#define Sdim 4096
#define Hdim 1024
#define Mrows (Bdim * Sdim)        // 16384
#define BSH   (Mrows * Hdim)
#define CHUNKS 64
#define CLEN   64

// -------------------- scratch (static __device__, no allocs) ---------------
__device__ __half g_x1[BSH];
__device__ __half g_y1[BSH];
__device__ __half g_w51[5 * Hdim * Hdim];
__device__ __half g_wo1[Hdim * Hdim];
__device__ float g_cont[BSH];
__device__ float g_ret[BSH];
__device__ float g_wg[BSH];
__device__ float g_rg[BSH];
__device__ float g_sk[BSH];
__device__ float g_Ac[Bdim * CHUNKS * Hdim];
__device__ float g_Bc[Bdim * CHUNKS * Hdim];
__device__ float g_Ss[Bdim * CHUNKS * Hdim];
__device__ float g_maskf[Mrows];
__device__ int   g_mask_mode;
__device__ float g_fs_dummy[Bdim * Hdim];

// -------------------- mask dtype detection + expansion ---------------------
__global__ void detect_mask_kernel(const unsigned char* __restrict__ mb, int n) {
    __shared__ int cflag[4];
    int t = threadIdx.x;
    if (t < 4) cflag[t] = 0;
    __syncthreads();
    for (int i = t; i < n; i += blockDim.x)
        if (mb[i]) atomicOr(&cflag[i & 3], 1);
    __syncthreads();
    if (t == 0) {
        int c0 = cflag[0], c1 = cflag[1], c2 = cflag[2], c3 = cflag[3];
        int mode = 0;
        if (c0 | c1 | c2 | c3) {
            if (c0 && !c1 && !c2 && !c3) mode = 1;
            else if (!c0 && !c1 && (c2 | c3)) mode = 2;
        }
        g_mask_mode = mode;
    }
}

__global__ void expand_mask_kernel(const void* __restrict__ mraw, int n) {
    int i = blockIdx.x * blockDim.x + threadIdx.x;
    if (i >= n) return;
    int mode = g_mask_mode;
    bool m;
    if (mode == 1)      m = ((const int*)mraw)[i] != 0;
    else if (mode == 2) m = ((const float*)mraw)[i] != 0.0f;
    else                m = ((const unsigned char*)mraw)[i] != 0;
    g_maskf[i] = m ? 1.0f : 0.0f;
}

// -------------------- fp32 -> fp16 conversion -------------------------------
__global__ void cvt_h_kernel(const float* __restrict__ in,
                             __half* __restrict__ o, int n) {
    int i = (blockIdx.x * blockDim.x + threadIdx.x) * 4;
    if (i >= n) return;
    float4 v = *(const float4*)(in + i);
    ((__half2*)(o + i))[0] = __halves2half2(__float2half_rn(v.x), __float2half_rn(v.y));
    ((__half2*)(o + i))[1] = __halves2half2(__float2half_rn(v.z), __float2half_rn(v.w));
}

// -------------------- PTX helpers ------------------------------------------
__device__ __forceinline__ uint32_t su32(const void* p) {
    uint32_t a;
    asm("{ .reg .u64 t; cvta.to.shared.u64 t, %1; cvt.u32.u64 %0, t; }"
        : "=r"(a) : "l"(p));
    return a;
}
__device__ __forceinline__ void cpa16(uint32_t s, const void* g) {
    asm volatile("cp.async.cg.shared.global [%0], [%1], 16;" :: "r"(s), "l"(g));
}
__device__ __forceinline__ void cpa_commit() {
    asm volatile("cp.async.commit_group;" ::: "memory");
}
__device__ __forceinline__ void cpa_wait1() {
    asm volatile("cp.async.wait_group 1;" ::: "memory");
}
__device__ __forceinline__ void cpa_wait0() {
    asm volatile("cp.async.wait_group 0;" ::: "memory");
}
__device__ __forceinline__ void ldm_x4(uint32_t* r, uint32_t addr) {
    asm volatile("ldmatrix.sync.aligned.m8n8.x4.shared.b16 {%0,%1,%2,%3}, [%4];"
                 : "=r"(r[0]), "=r"(r[1]), "=r"(r[2]), "=r"(r[3]) : "r"(addr));
}
__device__ __forceinline__ void mma_f16(float* d, const uint32_t* a,
                                        const uint32_t* b) {
    asm volatile(
        "mma.sync.aligned.m16n8k16.row.col.f32.f16.f16.f32 "
        "{%0,%1,%2,%3}, {%4,%5,%6,%7}, {%8,%9}, {%0,%1,%2,%3};"
        : "+f"(d[0]), "+f"(d[1]), "+f"(d[2]), "+f"(d[3])
        : "r"(a[0]), "r"(a[1]), "r"(a[2]), "r"(a[3]), "r"(b[0]), "r"(b[1]));
}

// -------------------- GEMM: single-product fp16 ------------------------------
// BM=BN=128, BK=64, 256 threads, 8 warps (2x4 of 64x32), 3-stage pipeline,
// 2 CTAs/SM (stage smem 32KB x 3 = 96KB per CTA).

#define TILE_BYTES 16384
#define STAGE_BYTES 32768
#define SMEM_TOTAL (3 * STAGE_BYTES)   // 98304
#define NSTAGES (Hdim / 64)            // 16

struct GArgs {
    const __half *A1, *W1;
    float*       outp[5];
    const float* bias[5];
    int          act[5];      // 0 none, 1 tanh, 2 sigmoid(+bias)
};

__device__ __forceinline__ uint32_t sw128(uint32_t base, int row, int chunk) {
    return base + row * 128 + ((chunk ^ (row & 7)) << 4);
}

__global__ __launch_bounds__(256, 2)
void gemm_mma_kernel(GArgs ga) {
    extern __shared__ char smem[];
    uint32_t sb = su32(smem);
    int tid = threadIdx.x;
    int wid = tid >> 5, lane = tid & 31;
    int wm = wid >> 2, wn = wid & 3;           // 2 x 4 warp grid
    int m0 = wm * 64, n0 = wn * 32;            // warp tile 64x32

    int mBase = blockIdx.y * 128;
    int nBase = blockIdx.x * 128;
    const __half* pA = ga.A1 + (size_t)mBase * Hdim;
    const __half* pW = ga.W1 + (size_t)nBase * Hdim;

    float acc[4][4][4];
#pragma unroll
    for (int i = 0; i < 4; i++)
#pragma unroll
        for (int j = 0; j < 4; j++)
#pragma unroll
            for (int e = 0; e < 4; e++) acc[i][j][e] = 0.0f;

    auto load_stage = [&](int s) {
        uint32_t so = sb + (s % 3) * STAGE_BYTES;
        int k0 = s * 64;
#pragma unroll
        for (int i = 0; i < 8; i++) {
            int c = tid + i * 256;             // 0..2047
            int T = c >> 10;                   // 0=A 1=W
            int ct = c & 1023;
            int row = ct >> 3, col = ct & 7;
            const __half* src = T ? pW : pA;
            cpa16(sw128(so + T * TILE_BYTES, row, col),
                  src + (size_t)row * Hdim + k0 + col * 8);
        }
        cpa_commit();
    };

    load_stage(0);
    load_stage(1);

    // ldmatrix lane addressing (128B rows)
    int aRow = (lane & 15);
    int aKC  = (lane >> 4);
    int bRow = (lane & 7) + ((lane >> 4) << 3);
    int bKC  = (lane >> 3) & 1;

    for (int s = 0; s < NSTAGES; s++) {
        if (s + 1 < NSTAGES) cpa_wait1();
        else cpa_wait0();
        __syncthreads();
        if (s + 2 < NSTAGES) load_stage(s + 2);   // prefetch overlaps compute

        uint32_t so = sb + (s % 3) * STAGE_BYTES;
        uint32_t tA = so;
        uint32_t tW = so + TILE_BYTES;

#pragma unroll
        for (int kk = 0; kk < 4; kk++) {
            int kc = kk * 2;
            uint32_t b1[8];
#pragma unroll
            for (int half = 0; half < 2; half++)
                ldm_x4(b1 + half * 4, sw128(tW, n0 + half * 16 + bRow, kc + bKC));
#pragma unroll
            for (int mf = 0; mf < 4; mf++) {
                uint32_t a[4];
                ldm_x4(a, sw128(tA, m0 + mf * 16 + aRow, kc + aKC));
#pragma unroll
                for (int nf = 0; nf < 4; nf++)
                    mma_f16(acc[mf][nf], a, b1 + (nf >> 1) * 4 + (nf & 1) * 2);
            }
        }
    }

    // ---------------- epilogue: activation + fp32 store ----------------
    int p = nBase >> 10;
    float* __restrict__ outp = ga.outp[p];
    const float* __restrict__ bias = ga.bias[p];
    int act = ga.act[p];
    int ocol0 = (nBase & 1023) + n0;

#pragma unroll
    for (int mf = 0; mf < 4; mf++) {
#pragma unroll
        for (int rh = 0; rh < 2; rh++) {
            int m = mBase + m0 + mf * 16 + (lane >> 2) + rh * 8;
#pragma unroll
            for (int nf = 0; nf < 4; nf++) {
                int col = ocol0 + nf * 8 + (lane & 3) * 2;
                float v0 = acc[mf][nf][rh * 2 + 0];
                float v1 = acc[mf][nf][rh * 2 + 1];
                if (act == 1) {
                    v0 = tanhf(v0);
                    v1 = tanhf(v1);
                } else if (act == 2) {
                    v0 = 1.0f / (1.0f + expf(-(v0 + bias[col])));
                    v1 = 1.0f / (1.0f + expf(-(v1 + bias[col + 1])));
                }
                *(float2*)(outp + (size_t)m * Hdim + col) = make_float2(v0, v1);
            }
        }
    }
}

// -------------------- chunked parallel linear scan -------------------------
__global__ void scan_stage1() {
    int id = blockIdx.x * blockDim.x + threadIdx.x;
    int h = id & (Hdim - 1);
    int j = (id >> 10) & (CHUNKS - 1);
    int b = id >> 16;
    float A = 1.0f, Bc = 0.0f;
    size_t base = (size_t)b * Sdim * Hdim + h;
    int s0 = j * CLEN;
#pragma unroll 4
    for (int t = 0; t < CLEN; t++) {
        int s = s0 + t;
        size_t idx = base + (size_t)s * Hdim;
        float a  = g_ret[idx];
        float m  = g_maskf[b * Sdim + s];
        float bx = (1.0f - a) * g_wg[idx] * g_cont[idx];
        float aa = 1.0f + m * (a - 1.0f);
        float bb = m * bx;
        A *= aa;
        Bc = fmaf(aa, Bc, bb);
    }
    int cidx = (b * CHUNKS + j) * Hdim + h;
    g_Ac[cidx] = A;
    g_Bc[cidx] = Bc;
}

__global__ void scan_stage2(const float* __restrict__ state,
                            float* __restrict__ fs_out) {
    int id = blockIdx.x * blockDim.x + threadIdx.x;
    int h = id & (Hdim - 1);
    int b = id >> 10;
    float st = state[id];
#pragma unroll
    for (int j = 0; j < CHUNKS; j++) {
        int cidx = (b * CHUNKS + j) * Hdim + h;
        g_Ss[cidx] = st;
        st = fmaf(g_Ac[cidx], st, g_Bc[cidx]);
    }
    fs_out[id] = st;
}

__global__ void scan_stage3() {
    int id = blockIdx.x * blockDim.x + threadIdx.x;
    int h = id & (Hdim - 1);
    int j = (id >> 10) & (CHUNKS - 1);
    int b = id >> 16;
    float st = g_Ss[(b * CHUNKS + j) * Hdim + h];
    size_t base = (size_t)b * Sdim * Hdim + h;
    int s0 = j * CLEN;
#pragma unroll 4
    for (int t = 0; t < CLEN; t++) {
        int s = s0 + t;
        size_t idx = base + (size_t)s * Hdim;
        float a  = g_ret[idx];
        float m  = g_maskf[b * Sdim + s];
        float bx = (1.0f - a) * g_wg[idx] * g_cont[idx];
        float aa = 1.0f + m * (a - 1.0f);
        float bb = m * bx;
        st = fmaf(aa, st, bb);
        float yv = m * fmaf(g_rg[idx], st, g_sk[idx]);
        g_y1[idx] = __float2half_rn(yv);
    }
}

// -------------------- launch -----------------------------------------------
extern "C" void kernel_launch(void* const* d_in, const int* in_sizes, int n_in,
                              void* d_out, int out_size) {
    const float* x     = (const float*)d_in[0];
    const float* state = (const float*)d_in[1];
    const void*  mask  = d_in[2];
    const float* W_in  = (const float*)d_in[3];
    const float* W_a   = (const float*)d_in[4];
    const float* b_a   = (const float*)d_in[5];
    const float* W_b   = (const float*)d_in[6];
    const float* b_b   = (const float*)d_in[7];
    const float* W_c   = (const float*)d_in[8];
    const float* b_c   = (const float*)d_in[9];
    const float* W_d   = (const float*)d_in[10];
    const float* W_out = (const float*)d_in[11];
    float* out = (float*)d_out;

    __half *p_x1, *p_y1, *p_w51, *p_wo1;
    float *p_cont, *p_ret, *p_wg, *p_rg, *p_sk, *p_fsdummy;
    cudaGetSymbolAddress((void**)&p_x1,  g_x1);
    cudaGetSymbolAddress((void**)&p_y1,  g_y1);
    cudaGetSymbolAddress((void**)&p_w51, g_w51);
    cudaGetSymbolAddress((void**)&p_wo1, g_wo1);
    cudaGetSymbolAddress((void**)&p_cont, g_cont);
    cudaGetSymbolAddress((void**)&p_ret,  g_ret);
    cudaGetSymbolAddress((void**)&p_wg,   g_wg);
    cudaGetSymbolAddress((void**)&p_rg,   g_rg);
    cudaGetSymbolAddress((void**)&p_sk,   g_sk);
    cudaGetSymbolAddress((void**)&p_fsdummy, g_fs_dummy);

    cudaFuncSetAttribute(gemm_mma_kernel,
                         cudaFuncAttributeMaxDynamicSharedMemorySize, SMEM_TOTAL);

    // mask canonicalization
    detect_mask_kernel<<<1, 256>>>((const unsigned char*)mask, Mrows);
    expand_mask_kernel<<<Mrows / 256, 256>>>(mask, Mrows);

    // conversions
    const size_t WN = (size_t)Hdim * Hdim;
    cvt_h_kernel<<<BSH / 4 / 256, 256>>>(x, p_x1, BSH);
    cvt_h_kernel<<<WN / 4 / 256, 256>>>(W_in, p_w51 + 0 * WN, WN);
    cvt_h_kernel<<<WN / 4 / 256, 256>>>(W_a,  p_w51 + 1 * WN, WN);
    cvt_h_kernel<<<WN / 4 / 256, 256>>>(W_b,  p_w51 + 2 * WN, WN);
    cvt_h_kernel<<<WN / 4 / 256, 256>>>(W_c,  p_w51 + 3 * WN, WN);
    cvt_h_kernel<<<WN / 4 / 256, 256>>>(W_d,  p_w51 + 4 * WN, WN);
    cvt_h_kernel<<<WN / 4 / 256, 256>>>(W_out, p_wo1, WN);

    // Phase 1: fused 5-projection GEMM
    GArgs g1;
    g1.A1 = p_x1; g1.W1 = p_w51;
    g1.outp[0] = p_cont; g1.outp[1] = p_ret; g1.outp[2] = p_wg;
    g1.outp[3] = p_rg;   g1.outp[4] = p_sk;
    g1.bias[0] = nullptr; g1.bias[1] = b_a; g1.bias[2] = b_b;
    g1.bias[3] = b_c;     g1.bias[4] = nullptr;
    g1.act[0] = 1; g1.act[1] = 2; g1.act[2] = 2; g1.act[3] = 2; g1.act[4] = 0;
    gemm_mma_kernel<<<dim3(40, 128), 256, SMEM_TOTAL>>>(g1);

    // Phase 2: chunked scan
    float* fsPtr = (out_size >= BSH + Bdim * Hdim) ? (out + BSH) : p_fsdummy;
    scan_stage1<<<(Bdim * CHUNKS * Hdim) / 256, 256>>>();
    scan_stage2<<<(Bdim * Hdim) / 256, 256>>>(state, fsPtr);
    scan_stage3<<<(Bdim * CHUNKS * Hdim) / 256, 256>>>();

    // Phase 3: output GEMM
    GArgs g2;
    g2.A1 = p_y1; g2.W1 = p_wo1;
    for (int i = 0; i < 5; i++) {
        g2.outp[i] = out; g2.bias[i] = nullptr; g2.act[i] = 0;
    }
    gemm_mma_kernel<<<dim3(8, 128), 256, SMEM_TOTAL>>>(g2);
}

// round 9
// speedup vs baseline: 2.9607x; 1.0066x over previous
#include <cuda_runtime.h>
#include <cuda_bf16.h>
#include <cuda_fp16.h>
#include <math.h>
#include <stdint.h>

// ---------------------------------------------------------------------------
// Mamba2 block: single-product fp16 HMMA GEMMs + fp16 gate storage + scan
// ---------------------------------------------------------------------------

#define Bdim 4
#define Sdim 4096
#define Hdim 1024
#define Mrows (Bdim * Sdim)        // 16384
#define BSH   (Mrows * Hdim)
#define CHUNKS 64
#define CLEN   64

// -------------------- scratch (static __device__, no allocs) ---------------
__device__ __half g_x1[BSH];
__device__ __half g_y1[BSH];
__device__ __half g_w51[5 * Hdim * Hdim];
__device__ __half g_wo1[Hdim * Hdim];
__device__ __half g_cont[BSH];
__device__ __half g_ret[BSH];
__device__ __half g_wg[BSH];
__device__ __half g_rg[BSH];
__device__ float g_sk[BSH];
__device__ float g_Ac[Bdim * CHUNKS * Hdim];
__device__ float g_Bc[Bdim * CHUNKS * Hdim];
__device__ float g_Ss[Bdim * CHUNKS * Hdim];
__device__ float g_maskf[Mrows];
__device__ int   g_mask_mode;
__device__ float g_fs_dummy[Bdim * Hdim];

// -------------------- mask dtype detection + expansion ---------------------
__global__ void detect_mask_kernel(const unsigned char* __restrict__ mb, int n) {
    __shared__ int cflag[4];
    int t = threadIdx.x;
    if (t < 4) cflag[t] = 0;
    __syncthreads();
    for (int i = t; i < n; i += blockDim.x)
        if (mb[i]) atomicOr(&cflag[i & 3], 1);
    __syncthreads();
    if (t == 0) {
        int c0 = cflag[0], c1 = cflag[1], c2 = cflag[2], c3 = cflag[3];
        int mode = 0;
        if (c0 | c1 | c2 | c3) {
            if (c0 && !c1 && !c2 && !c3) mode = 1;
            else if (!c0 && !c1 && (c2 | c3)) mode = 2;
        }
        g_mask_mode = mode;
    }
}

__global__ void expand_mask_kernel(const void* __restrict__ mraw, int n) {
    int i = blockIdx.x * blockDim.x + threadIdx.x;
    if (i >= n) return;
    int mode = g_mask_mode;
    bool m;
    if (mode == 1)      m = ((const int*)mraw)[i] != 0;
    else if (mode == 2) m = ((const float*)mraw)[i] != 0.0f;
    else                m = ((const unsigned char*)mraw)[i] != 0;
    g_maskf[i] = m ? 1.0f : 0.0f;
}

// -------------------- fp32 -> fp16 conversions ------------------------------
__global__ void cvt_h_kernel(const float* __restrict__ in,
                             __half* __restrict__ o, int n) {
    int i = (blockIdx.x * blockDim.x + threadIdx.x) * 4;
    if (i >= n) return;
    float4 v = *(const float4*)(in + i);
    ((__half2*)(o + i))[0] = __halves2half2(__float2half_rn(v.x), __float2half_rn(v.y));
    ((__half2*)(o + i))[1] = __halves2half2(__float2half_rn(v.z), __float2half_rn(v.w));
}

struct CvtWArgs { const float* src[6]; __half* dst[6]; };
// 6 weight matrices, 1M elements each; blockIdx.x>>10 selects matrix.
__global__ void cvt_w_all_kernel(CvtWArgs a) {
    int which = blockIdx.x >> 10;
    int i = ((blockIdx.x & 1023) * blockDim.x + threadIdx.x) * 4;
    const float* in = a.src[which];
    __half* o = a.dst[which];
    float4 v = *(const float4*)(in + i);
    ((__half2*)(o + i))[0] = __halves2half2(__float2half_rn(v.x), __float2half_rn(v.y));
    ((__half2*)(o + i))[1] = __halves2half2(__float2half_rn(v.z), __float2half_rn(v.w));
}

// -------------------- PTX helpers ------------------------------------------
__device__ __forceinline__ uint32_t su32(const void* p) {
    uint32_t a;
    asm("{ .reg .u64 t; cvta.to.shared.u64 t, %1; cvt.u32.u64 %0, t; }"
        : "=r"(a) : "l"(p));
    return a;
}
__device__ __forceinline__ void cpa16(uint32_t s, const void* g) {
    asm volatile("cp.async.cg.shared.global [%0], [%1], 16;" :: "r"(s), "l"(g));
}
__device__ __forceinline__ void cpa_commit() {
    asm volatile("cp.async.commit_group;" ::: "memory");
}
__device__ __forceinline__ void cpa_wait1() {
    asm volatile("cp.async.wait_group 1;" ::: "memory");
}
__device__ __forceinline__ void cpa_wait0() {
    asm volatile("cp.async.wait_group 0;" ::: "memory");
}
__device__ __forceinline__ void ldm_x4(uint32_t* r, uint32_t addr) {
    asm volatile("ldmatrix.sync.aligned.m8n8.x4.shared.b16 {%0,%1,%2,%3}, [%4];"
                 : "=r"(r[0]), "=r"(r[1]), "=r"(r[2]), "=r"(r[3]) : "r"(addr));
}
__device__ __forceinline__ void mma_f16(float* d, const uint32_t* a,
                                        const uint32_t* b) {
    asm volatile(
        "mma.sync.aligned.m16n8k16.row.col.f32.f16.f16.f32 "
        "{%0,%1,%2,%3}, {%4,%5,%6,%7}, {%8,%9}, {%0,%1,%2,%3};"
        : "+f"(d[0]), "+f"(d[1]), "+f"(d[2]), "+f"(d[3])
        : "r"(a[0]), "r"(a[1]), "r"(a[2]), "r"(a[3]), "r"(b[0]), "r"(b[1]));
}

// -------------------- GEMM: single-product fp16 ------------------------------
// BM=BN=128, BK=64, 256 threads, 8 warps (2x4 of 64x32), 3-stage pipeline,
// 2 CTAs/SM (stage smem 32KB x 3 = 96KB per CTA).

#define TILE_BYTES 16384
#define STAGE_BYTES 32768
#define SMEM_TOTAL (3 * STAGE_BYTES)   // 98304
#define NSTAGES (Hdim / 64)            // 16

struct GArgs {
    const __half *A1, *W1;
    void*        outp[5];
    const float* bias[5];
    int          act[5];      // 0 none, 1 tanh, 2 sigmoid(+bias)
    int          half_out[5]; // 1 -> store __half, 0 -> store float
};

__device__ __forceinline__ uint32_t sw128(uint32_t base, int row, int chunk) {
    return base + row * 128 + ((chunk ^ (row & 7)) << 4);
}

__global__ __launch_bounds__(256, 2)
void gemm_mma_kernel(GArgs ga) {
    extern __shared__ char smem[];
    uint32_t sb = su32(smem);
    int tid = threadIdx.x;
    int wid = tid >> 5, lane = tid & 31;
    int wm = wid >> 2, wn = wid & 3;           // 2 x 4 warp grid
    int m0 = wm * 64, n0 = wn * 32;            // warp tile 64x32

    int mBase = blockIdx.y * 128;
    int nBase = blockIdx.x * 128;
    const __half* pA = ga.A1 + (size_t)mBase * Hdim;
    const __half* pW = ga.W1 + (size_t)nBase * Hdim;

    float acc[4][4][4];
#pragma unroll
    for (int i = 0; i < 4; i++)
#pragma unroll
        for (int j = 0; j < 4; j++)
#pragma unroll
            for (int e = 0; e < 4; e++) acc[i][j][e] = 0.0f;

    auto load_stage = [&](int s) {
        uint32_t so = sb + (s % 3) * STAGE_BYTES;
        int k0 = s * 64;
#pragma unroll
        for (int i = 0; i < 8; i++) {
            int c = tid + i * 256;             // 0..2047
            int T = c >> 10;                   // 0=A 1=W
            int ct = c & 1023;
            int row = ct >> 3, col = ct & 7;
            const __half* src = T ? pW : pA;
            cpa16(sw128(so + T * TILE_BYTES, row, col),
                  src + (size_t)row * Hdim + k0 + col * 8);
        }
        cpa_commit();
    };

    load_stage(0);
    load_stage(1);

    int aRow = (lane & 15);
    int aKC  = (lane >> 4);
    int bRow = (lane & 7) + ((lane >> 4) << 3);
    int bKC  = (lane >> 3) & 1;

    for (int s = 0; s < NSTAGES; s++) {
        if (s + 1 < NSTAGES) cpa_wait1();
        else cpa_wait0();
        __syncthreads();
        if (s + 2 < NSTAGES) load_stage(s + 2);   // prefetch overlaps compute

        uint32_t so = sb + (s % 3) * STAGE_BYTES;
        uint32_t tA = so;
        uint32_t tW = so + TILE_BYTES;

#pragma unroll
        for (int kk = 0; kk < 4; kk++) {
            int kc = kk * 2;
            uint32_t b1[8];
#pragma unroll
            for (int half = 0; half < 2; half++)
                ldm_x4(b1 + half * 4, sw128(tW, n0 + half * 16 + bRow, kc + bKC));
#pragma unroll
            for (int mf = 0; mf < 4; mf++) {
                uint32_t a[4];
                ldm_x4(a, sw128(tA, m0 + mf * 16 + aRow, kc + aKC));
#pragma unroll
                for (int nf = 0; nf < 4; nf++)
                    mma_f16(acc[mf][nf], a, b1 + (nf >> 1) * 4 + (nf & 1) * 2);
            }
        }
    }

    // ---------------- epilogue: activation + store ----------------
    int p = nBase >> 10;
    const float* __restrict__ bias = ga.bias[p];
    int act = ga.act[p];
    int hout = ga.half_out[p];
    int ocol0 = (nBase & 1023) + n0;

#pragma unroll
    for (int mf = 0; mf < 4; mf++) {
#pragma unroll
        for (int rh = 0; rh < 2; rh++) {
            int m = mBase + m0 + mf * 16 + (lane >> 2) + rh * 8;
#pragma unroll
            for (int nf = 0; nf < 4; nf++) {
                int col = ocol0 + nf * 8 + (lane & 3) * 2;
                float v0 = acc[mf][nf][rh * 2 + 0];
                float v1 = acc[mf][nf][rh * 2 + 1];
                if (act == 1) {
                    v0 = tanhf(v0);
                    v1 = tanhf(v1);
                } else if (act == 2) {
                    v0 = 1.0f / (1.0f + expf(-(v0 + bias[col])));
                    v1 = 1.0f / (1.0f + expf(-(v1 + bias[col + 1])));
                }
                if (hout) {
                    __half* op = (__half*)ga.outp[p];
                    *(__half2*)(op + (size_t)m * Hdim + col) =
                        __halves2half2(__float2half_rn(v0), __float2half_rn(v1));
                } else {
                    float* op = (float*)ga.outp[p];
                    *(float2*)(op + (size_t)m * Hdim + col) = make_float2(v0, v1);
                }
            }
        }
    }
}

// -------------------- chunked parallel linear scan -------------------------
__global__ void scan_stage1() {
    int id = blockIdx.x * blockDim.x + threadIdx.x;
    int h = id & (Hdim - 1);
    int j = (id >> 10) & (CHUNKS - 1);
    int b = id >> 16;
    float A = 1.0f, Bc = 0.0f;
    size_t base = (size_t)b * Sdim * Hdim + h;
    int s0 = j * CLEN;
#pragma unroll 4
    for (int t = 0; t < CLEN; t++) {
        int s = s0 + t;
        size_t idx = base + (size_t)s * Hdim;
        float a  = __half2float(g_ret[idx]);
        float m  = g_maskf[b * Sdim + s];
        float bx = (1.0f - a) * __half2float(g_wg[idx]) * __half2float(g_cont[idx]);
        float aa = 1.0f + m * (a - 1.0f);
        float bb = m * bx;
        A *= aa;
        Bc = fmaf(aa, Bc, bb);
    }
    int cidx = (b * CHUNKS + j) * Hdim + h;
    g_Ac[cidx] = A;
    g_Bc[cidx] = Bc;
}

__global__ void scan_stage2(const float* __restrict__ state,
                            float* __restrict__ fs_out) {
    int id = blockIdx.x * blockDim.x + threadIdx.x;
    int h = id & (Hdim - 1);
    int b = id >> 10;
    float st = state[id];
#pragma unroll
    for (int j = 0; j < CHUNKS; j++) {
        int cidx = (b * CHUNKS + j) * Hdim + h;
        g_Ss[cidx] = st;
        st = fmaf(g_Ac[cidx], st, g_Bc[cidx]);
    }
    fs_out[id] = st;
}

__global__ void scan_stage3() {
    int id = blockIdx.x * blockDim.x + threadIdx.x;
    int h = id & (Hdim - 1);
    int j = (id >> 10) & (CHUNKS - 1);
    int b = id >> 16;
    float st = g_Ss[(b * CHUNKS + j) * Hdim + h];
    size_t base = (size_t)b * Sdim * Hdim + h;
    int s0 = j * CLEN;
#pragma unroll 4
    for (int t = 0; t < CLEN; t++) {
        int s = s0 + t;
        size_t idx = base + (size_t)s * Hdim;
        float a  = __half2float(g_ret[idx]);
        float m  = g_maskf[b * Sdim + s];
        float bx = (1.0f - a) * __half2float(g_wg[idx]) * __half2float(g_cont[idx]);
        float aa = 1.0f + m * (a - 1.0f);
        float bb = m * bx;
        st = fmaf(aa, st, bb);
        float yv = m * fmaf(__half2float(g_rg[idx]), st, g_sk[idx]);
        g_y1[idx] = __float2half_rn(yv);
    }
}

// -------------------- launch -----------------------------------------------
extern "C" void kernel_launch(void* const* d_in, const int* in_sizes, int n_in,
                              void* d_out, int out_size) {
    const float* x     = (const float*)d_in[0];
    const float* state = (const float*)d_in[1];
    const void*  mask  = d_in[2];
    const float* W_in  = (const float*)d_in[3];
    const float* W_a   = (const float*)d_in[4];
    const float* b_a   = (const float*)d_in[5];
    const float* W_b   = (const float*)d_in[6];
    const float* b_b   = (const float*)d_in[7];
    const float* W_c   = (const float*)d_in[8];
    const float* b_c   = (const float*)d_in[9];
    const float* W_d   = (const float*)d_in[10];
    const float* W_out = (const float*)d_in[11];
    float* out = (float*)d_out;

    __half *p_x1, *p_y1, *p_w51, *p_wo1, *p_cont, *p_ret, *p_wg, *p_rg;
    float *p_sk, *p_fsdummy;
    cudaGetSymbolAddress((void**)&p_x1,  g_x1);
    cudaGetSymbolAddress((void**)&p_y1,  g_y1);
    cudaGetSymbolAddress((void**)&p_w51, g_w51);
    cudaGetSymbolAddress((void**)&p_wo1, g_wo1);
    cudaGetSymbolAddress((void**)&p_cont, g_cont);
    cudaGetSymbolAddress((void**)&p_ret,  g_ret);
    cudaGetSymbolAddress((void**)&p_wg,   g_wg);
    cudaGetSymbolAddress((void**)&p_rg,   g_rg);
    cudaGetSymbolAddress((void**)&p_sk,   g_sk);
    cudaGetSymbolAddress((void**)&p_fsdummy, g_fs_dummy);

    cudaFuncSetAttribute(gemm_mma_kernel,
                         cudaFuncAttributeMaxDynamicSharedMemorySize, SMEM_TOTAL);

    // mask canonicalization
    detect_mask_kernel<<<1, 256>>>((const unsigned char*)mask, Mrows);
    expand_mask_kernel<<<Mrows / 256, 256>>>(mask, Mrows);

    // conversions
    const size_t WN = (size_t)Hdim * Hdim;
    cvt_h_kernel<<<BSH / 4 / 256, 256>>>(x, p_x1, BSH);
    CvtWArgs cw;
    cw.src[0] = W_in;  cw.dst[0] = p_w51 + 0 * WN;
    cw.src[1] = W_a;   cw.dst[1] = p_w51 + 1 * WN;
    cw.src[2] = W_b;   cw.dst[2] = p_w51 + 2 * WN;
    cw.src[3] = W_c;   cw.dst[3] = p_w51 + 3 * WN;
    cw.src[4] = W_d;   cw.dst[4] = p_w51 + 4 * WN;
    cw.src[5] = W_out; cw.dst[5] = p_wo1;
    cvt_w_all_kernel<<<6 * 1024, 256>>>(cw);

    // Phase 1: fused 5-projection GEMM
    GArgs g1;
    g1.A1 = p_x1; g1.W1 = p_w51;
    g1.outp[0] = p_cont; g1.outp[1] = p_ret; g1.outp[2] = p_wg;
    g1.outp[3] = p_rg;   g1.outp[4] = p_sk;
    g1.bias[0] = nullptr; g1.bias[1] = b_a; g1.bias[2] = b_b;
    g1.bias[3] = b_c;     g1.bias[4] = nullptr;
    g1.act[0] = 1; g1.act[1] = 2; g1.act[2] = 2; g1.act[3] = 2; g1.act[4] = 0;
    g1.half_out[0] = 1; g1.half_out[1] = 1; g1.half_out[2] = 1;
    g1.half_out[3] = 1; g1.half_out[4] = 0;
    gemm_mma_kernel<<<dim3(40, 128), 256, SMEM_TOTAL>>>(g1);

    // Phase 2: chunked scan
    float* fsPtr = (out_size >= BSH + Bdim * Hdim) ? (out + BSH) : p_fsdummy;
    scan_stage1<<<(Bdim * CHUNKS * Hdim) / 256, 256>>>();
    scan_stage2<<<(Bdim * Hdim) / 256, 256>>>(state, fsPtr);
    scan_stage3<<<(Bdim * CHUNKS * Hdim) / 256, 256>>>();

    // Phase 3: output GEMM
    GArgs g2;
    g2.A1 = p_y1; g2.W1 = p_wo1;
    for (int i = 0; i < 5; i++) {
        g2.outp[i] = out; g2.bias[i] = nullptr; g2.act[i] = 0; g2.half_out[i] = 0;
    }
    gemm_mma_kernel<<<dim3(8, 128), 256, SMEM_TOTAL>>>(g2);
}